// round 1
// baseline (speedup 1.0000x reference)
#include <cuda_runtime.h>
#include <cfloat>

// ResidualVectorQuantizer: B=16,E=64,H=64,W=64, K=1024, NC=8
// N = 65536 tokens. One thread per token; 8 stages fused in one kernel.
// Numerics replicate the reference fp32 exactly-as-hypothesized:
//   r2   = sequential sum of rounded squares of res
//   dot  = sequential fused-FMA over e
//   cb2  = sequential sum of rounded squares of cb row
//   d    = fl(fl(r2 - fl(2*dot)) + cb2), argmin with first-index tie-break
//   res -= q (rounded elementwise), quant += q sequentially per stage.

#define NTOK  65536
#define EDIM  64
#define KCB   1024
#define NCODE 8
#define KT    128      // codebook k-tile in smem
#define PITCH 132      // padded row pitch (floats) for transposed tile
#define TPB   256

__global__ __launch_bounds__(TPB, 1)
void rvq_kernel(const float* __restrict__ emb,
                const float* __restrict__ cb,
                float* __restrict__ out)
{
    __shared__ float cbs[EDIM * PITCH];   // transposed tile: cbs[e][k]
    __shared__ float cb2s[KT];

    const int tid = threadIdx.x;
    const int n   = blockIdx.x * TPB + tid;       // token id
    const int b   = n >> 12;                      // n / (H*W)
    const int hw  = n & 4095;                     // h*W + w

    const float* ep = emb + (size_t)b * (EDIM * 4096) + hw;

    float res[EDIM];
    float quant[EDIM];
#pragma unroll
    for (int e = 0; e < EDIM; e++) {
        res[e]   = ep[(size_t)e * 4096];
        quant[e] = 0.0f;
    }

    for (int s = 0; s < NCODE; s++) {
        const float* cbase = cb + (size_t)s * KCB * EDIM;

        // r2 = sum(res*res), rounded square then sequential add (no FMA fusion)
        float r2 = 0.0f;
#pragma unroll
        for (int e = 0; e < EDIM; e++)
            r2 = __fadd_rn(r2, __fmul_rn(res[e], res[e]));

        float min_d = FLT_MAX;
        int   min_i = 0;

        for (int kt = 0; kt < KCB; kt += KT) {
            __syncthreads();
            // cooperative load of codebook tile, transposed into smem
            {
                const float4* g = (const float4*)(cbase + (size_t)kt * EDIM);
                for (int i = tid; i < (KT * EDIM / 4); i += TPB) {
                    int k  = i >> 4;      // 0..127
                    int e4 = i & 15;      // 0..15 (groups of 4 e)
                    float4 v = g[k * 16 + e4];
                    cbs[(e4 * 4 + 0) * PITCH + k] = v.x;
                    cbs[(e4 * 4 + 1) * PITCH + k] = v.y;
                    cbs[(e4 * 4 + 2) * PITCH + k] = v.z;
                    cbs[(e4 * 4 + 3) * PITCH + k] = v.w;
                }
            }
            __syncthreads();
            // per-tile cb2: sequential sum of rounded squares
            if (tid < KT) {
                float c2 = 0.0f;
#pragma unroll
                for (int e = 0; e < EDIM; e++) {
                    float v = cbs[e * PITCH + tid];
                    c2 = __fadd_rn(c2, __fmul_rn(v, v));
                }
                cb2s[tid] = c2;
            }
            __syncthreads();

            // main distance loop: 8 codewords at a time
            for (int k0 = 0; k0 < KT; k0 += 8) {
                float dot[8];
#pragma unroll
                for (int j = 0; j < 8; j++) dot[j] = 0.0f;

#pragma unroll
                for (int e = 0; e < EDIM; e++) {
                    float r = res[e];
                    const float4* row = (const float4*)(cbs + e * PITCH + k0);
                    float4 c0 = row[0];
                    float4 c1 = row[1];
                    dot[0] = __fmaf_rn(r, c0.x, dot[0]);
                    dot[1] = __fmaf_rn(r, c0.y, dot[1]);
                    dot[2] = __fmaf_rn(r, c0.z, dot[2]);
                    dot[3] = __fmaf_rn(r, c0.w, dot[3]);
                    dot[4] = __fmaf_rn(r, c1.x, dot[4]);
                    dot[5] = __fmaf_rn(r, c1.y, dot[5]);
                    dot[6] = __fmaf_rn(r, c1.z, dot[6]);
                    dot[7] = __fmaf_rn(r, c1.w, dot[7]);
                }
#pragma unroll
                for (int j = 0; j < 8; j++) {
                    float d = __fadd_rn(__fsub_rn(r2, __fmul_rn(2.0f, dot[j])),
                                        cb2s[k0 + j]);
                    if (d < min_d) { min_d = d; min_i = kt + k0 + j; }
                }
            }
        }

        // gather chosen codeword; update residual and accumulate quant
        const float4* q4 = (const float4*)(cbase + (size_t)min_i * EDIM);
#pragma unroll
        for (int i = 0; i < 16; i++) {
            float4 q = q4[i];
            res[4*i+0]   = __fsub_rn(res[4*i+0],   q.x);
            res[4*i+1]   = __fsub_rn(res[4*i+1],   q.y);
            res[4*i+2]   = __fsub_rn(res[4*i+2],   q.z);
            res[4*i+3]   = __fsub_rn(res[4*i+3],   q.w);
            quant[4*i+0] = __fadd_rn(quant[4*i+0], q.x);
            quant[4*i+1] = __fadd_rn(quant[4*i+1], q.y);
            quant[4*i+2] = __fadd_rn(quant[4*i+2], q.z);
            quant[4*i+3] = __fadd_rn(quant[4*i+3], q.w);
        }
    }

    float* op = out + (size_t)b * (EDIM * 4096) + hw;
#pragma unroll
    for (int e = 0; e < EDIM; e++)
        op[(size_t)e * 4096] = quant[e];
}

extern "C" void kernel_launch(void* const* d_in, const int* in_sizes, int n_in,
                              void* d_out, int out_size)
{
    const float* emb = (const float*)d_in[0];   // [16,64,64,64] fp32
    const float* cb  = (const float*)d_in[1];   // [8,1024,64]  fp32
    float* out = (float*)d_out;                 // [16,64,64,64] fp32
    (void)in_sizes; (void)n_in; (void)out_size;

    rvq_kernel<<<NTOK / TPB, TPB>>>(emb, cb, out);
}

// round 2
// speedup vs baseline: 1.0501x; 1.0501x over previous
#include <cuda_runtime.h>
#include <cfloat>

// ResidualVectorQuantizer: B=16,E=64,H=64,W=64, K=1024, NC=8, N=65536 tokens.
// One thread per token; 8 stages fused. Bitwise-exact reference numerics:
//   r2  = sequential sum of rounded squares of res
//   dot = sequential fused-FMA over e
//   cb2 = sequential sum of rounded squares of cb row (precomputed kernel)
//   d   = fl(fl(r2 - fl(2*dot)) + cb2), argmin first-index tie-break
//   res -= q elementwise rounded; quant = ((q0+q1)+q2)... recomputed at end
//   (bitwise identical to per-stage accumulation since 0+q0 == q0).

#define NTOK  65536
#define EDIM  64
#define KCB   1024
#define NCODE 8
#define KT    128      // codebook k-tile in smem
#define PITCH 132      // padded row pitch (floats) for transposed tile
#define TPB   256

__device__ float g_cb2[NCODE * KCB];

__global__ void cb2_kernel(const float* __restrict__ cb)
{
    const int i = blockIdx.x * blockDim.x + threadIdx.x;   // 0 .. 8191
    const float* row = cb + (size_t)i * EDIM;
    float c2 = 0.0f;
#pragma unroll
    for (int e = 0; e < EDIM; e++)
        c2 = __fadd_rn(c2, __fmul_rn(row[e], row[e]));
    g_cb2[i] = c2;
}

__global__ __launch_bounds__(TPB, 2)
void rvq_kernel(const float* __restrict__ emb,
                const float* __restrict__ cb,
                float* __restrict__ out)
{
    __shared__ float cbs[EDIM * PITCH];   // transposed tile: cbs[e][k]
    __shared__ float cb2s[KT];

    const int tid = threadIdx.x;
    const int n   = blockIdx.x * TPB + tid;       // token id
    const int b   = n >> 12;                      // n / (H*W)
    const int hw  = n & 4095;                     // h*W + w

    const float* ep = emb + (size_t)b * (EDIM * 4096) + hw;

    float res[EDIM];
#pragma unroll
    for (int e = 0; e < EDIM; e++)
        res[e] = ep[(size_t)e * 4096];

    int idxs[NCODE];                              // chosen codeword per stage

#pragma unroll 1
    for (int s = 0; s < NCODE; s++) {
        const float* cbase = cb + (size_t)s * KCB * EDIM;

        // r2 = sequential sum of rounded squares (no FMA contraction)
        float r2 = 0.0f;
#pragma unroll
        for (int e = 0; e < EDIM; e++)
            r2 = __fadd_rn(r2, __fmul_rn(res[e], res[e]));

        float min_d = FLT_MAX;
        int   min_i = 0;

#pragma unroll 1
        for (int kt = 0; kt < KCB; kt += KT) {
            __syncthreads();
            // cooperative load of codebook tile, transposed into smem
            {
                const float4* g = (const float4*)(cbase + (size_t)kt * EDIM);
#pragma unroll
                for (int i = tid; i < (KT * EDIM / 4); i += TPB) {
                    int k  = i >> 4;      // 0..127
                    int e4 = i & 15;      // 0..15 (groups of 4 e)
                    float4 v = g[k * 16 + e4];
                    cbs[(e4 * 4 + 0) * PITCH + k] = v.x;
                    cbs[(e4 * 4 + 1) * PITCH + k] = v.y;
                    cbs[(e4 * 4 + 2) * PITCH + k] = v.z;
                    cbs[(e4 * 4 + 3) * PITCH + k] = v.w;
                }
            }
            if (tid < KT)
                cb2s[tid] = g_cb2[s * KCB + kt + tid];
            __syncthreads();

            // distance scan: 8 codewords at a time
#pragma unroll 1
            for (int k0 = 0; k0 < KT; k0 += 8) {
                float dot[8];
#pragma unroll
                for (int j = 0; j < 8; j++) dot[j] = 0.0f;

#pragma unroll
                for (int e = 0; e < EDIM; e++) {
                    float r = res[e];
                    const float4* row = (const float4*)(cbs + e * PITCH + k0);
                    float4 c0 = row[0];
                    float4 c1 = row[1];
                    dot[0] = __fmaf_rn(r, c0.x, dot[0]);
                    dot[1] = __fmaf_rn(r, c0.y, dot[1]);
                    dot[2] = __fmaf_rn(r, c0.z, dot[2]);
                    dot[3] = __fmaf_rn(r, c0.w, dot[3]);
                    dot[4] = __fmaf_rn(r, c1.x, dot[4]);
                    dot[5] = __fmaf_rn(r, c1.y, dot[5]);
                    dot[6] = __fmaf_rn(r, c1.z, dot[6]);
                    dot[7] = __fmaf_rn(r, c1.w, dot[7]);
                }
#pragma unroll
                for (int j = 0; j < 8; j++) {
                    float d = __fadd_rn(__fsub_rn(r2, __fmul_rn(2.0f, dot[j])),
                                        cb2s[k0 + j]);
                    if (d < min_d) { min_d = d; min_i = kt + k0 + j; }
                }
            }
        }

        idxs[s] = min_i;

        // residual update only (quant recomputed at the end from idxs)
        const float4* q4 = (const float4*)(cbase + (size_t)min_i * EDIM);
#pragma unroll
        for (int i = 0; i < 16; i++) {
            float4 q = q4[i];
            res[4*i+0] = __fsub_rn(res[4*i+0], q.x);
            res[4*i+1] = __fsub_rn(res[4*i+1], q.y);
            res[4*i+2] = __fsub_rn(res[4*i+2], q.z);
            res[4*i+3] = __fsub_rn(res[4*i+3], q.w);
        }
    }

    // quant = ((q0 + q1) + q2) ... + q7, bitwise == per-stage accumulation
    float* op = out + (size_t)b * (EDIM * 4096) + hw;
#pragma unroll 1
    for (int e4 = 0; e4 < 16; e4++) {
        const float4* q0 =
            (const float4*)(cb + ((size_t)0 * KCB + idxs[0]) * EDIM) + e4;
        float4 acc = *q0;
#pragma unroll
        for (int s = 1; s < NCODE; s++) {
            const float4* qs =
                (const float4*)(cb + ((size_t)s * KCB + idxs[s]) * EDIM) + e4;
            float4 q = *qs;
            acc.x = __fadd_rn(acc.x, q.x);
            acc.y = __fadd_rn(acc.y, q.y);
            acc.z = __fadd_rn(acc.z, q.z);
            acc.w = __fadd_rn(acc.w, q.w);
        }
        op[(size_t)(e4 * 4 + 0) * 4096] = acc.x;
        op[(size_t)(e4 * 4 + 1) * 4096] = acc.y;
        op[(size_t)(e4 * 4 + 2) * 4096] = acc.z;
        op[(size_t)(e4 * 4 + 3) * 4096] = acc.w;
    }
}

extern "C" void kernel_launch(void* const* d_in, const int* in_sizes, int n_in,
                              void* d_out, int out_size)
{
    const float* emb = (const float*)d_in[0];   // [16,64,64,64] fp32
    const float* cb  = (const float*)d_in[1];   // [8,1024,64]  fp32
    float* out = (float*)d_out;                 // [16,64,64,64] fp32
    (void)in_sizes; (void)n_in; (void)out_size;

    cb2_kernel<<<(NCODE * KCB) / 256, 256>>>(cb);
    rvq_kernel<<<NTOK / TPB, TPB>>>(emb, cb, out);
}

// round 3
// speedup vs baseline: 1.4779x; 1.4075x over previous
#include <cuda_runtime.h>
#include <cuda_fp16.h>
#include <cfloat>
#include <cstdint>

// ResidualVectorQuantizer, exact argmin via tf32-MMA prefilter + scalar verify.
// B=16,E=64,H=64,W=64 -> N=65536 tokens; K=1024, NC=8 stages.
//
// Exact reference numerics (validated rel_err==0 in rounds 1-2):
//   r2  = sequential sum of rounded squares of res (e ascending)
//   dot = sequential fused-FMA over e ascending
//   d   = fl(fl(r2 - fl(2*dot)) + cb2), argmin first-index tie-break
//   res -= q elementwise rounded; quant = ((q0+q1)+...)+q7
// MMA computes approximate scores t~ = cb2 - 2*dot~ (tf32); every k with
// t~ <= min + MARGIN is re-verified exactly. MARGIN=1e-3 >> worst-case
// |t~ - (d - r2)| <= ~1.4e-4 (tf32 trunc + fp16 store + assembly rounding),
// so the exact argmin is always in the candidate set.

#define NTOK   65536
#define EDIM   64
#define KCB    1024
#define NCODE  8
#define MTOK   64          // tokens per CTA
#define TPB    256
#define GTW    256         // codebook k-gtile width in smem
#define RPITCH 68          // res row pitch (floats): 16B-aligned, conflict-ok
#define SCP    1032        // score row pitch (halves)
#define CAP    64
#define MARGIN 1e-3f

__device__ float g_cbt[NCODE * EDIM * KCB];  // tf32-truncated, [s][e][k]
__device__ float g_cb2[NCODE * KCB];         // exact ||cb||^2

__device__ __forceinline__ unsigned f2tf32(float x) {
    unsigned r;
    asm("cvt.rna.tf32.f32 %0, %1;" : "=r"(r) : "f"(x));
    return r;
}

__device__ __forceinline__ float2 h2f(unsigned u) {
    __half2 h = *reinterpret_cast<__half2*>(&u);
    return __half22float2(h);
}

__device__ __forceinline__ void mma_tf32(float& c0, float& c1, float& c2, float& c3,
                                         unsigned a0, unsigned a1, unsigned a2, unsigned a3,
                                         unsigned b0, unsigned b1) {
    asm volatile(
        "mma.sync.aligned.m16n8k8.row.col.f32.tf32.tf32.f32 "
        "{%0,%1,%2,%3}, {%4,%5,%6,%7}, {%8,%9}, {%0,%1,%2,%3};\n"
        : "+f"(c0), "+f"(c1), "+f"(c2), "+f"(c3)
        : "r"(a0), "r"(a1), "r"(a2), "r"(a3), "r"(b0), "r"(b1));
}

// ---- precompute: exact cb2 ----
__global__ void cb2_kernel(const float* __restrict__ cb)
{
    const int i = blockIdx.x * blockDim.x + threadIdx.x;   // 0..8191
    const float* row = cb + (size_t)i * EDIM;
    float c2 = 0.0f;
#pragma unroll
    for (int e = 0; e < EDIM; e++)
        c2 = __fadd_rn(c2, __fmul_rn(row[e], row[e]));
    g_cb2[i] = c2;
}

// ---- precompute: transpose + tf32-truncate codebook to [s][e][k] ----
__global__ void cbt_kernel(const float* __restrict__ cb)
{
    __shared__ float tile[32][33];
    const int s  = blockIdx.z;
    const int n0 = blockIdx.x * 32;
    const int e0 = blockIdx.y * 32;
    const int tx = threadIdx.x, ty = threadIdx.y;
#pragma unroll
    for (int i = 0; i < 32; i += 8)
        tile[ty + i][tx] = cb[((size_t)s * KCB + (n0 + ty + i)) * EDIM + e0 + tx];
    __syncthreads();
#pragma unroll
    for (int i = 0; i < 32; i += 8) {
        unsigned t = f2tf32(tile[tx][ty + i]);
        g_cbt[((size_t)s * EDIM + (e0 + ty + i)) * KCB + n0 + tx] = __uint_as_float(t);
    }
}

struct Cand {
    int   cnt;
    int   pad[3];
    int   tok[CAP];
    int   kk[CAP];
    float dd[CAP];
};

// smem segment sizes (bytes)
#define SC_BYTES   (MTOK * SCP * 2)        // 132096
#define BS_BYTES   (EDIM * GTW * 4)        // 65536
#define RES_BYTES  (MTOK * RPITCH * 4)     // 17408
#define C2S_BYTES  (GTW * 4)               // 1024
#define CAND_BYTES (8 * (int)sizeof(Cand)) // 6272
#define R2S_BYTES  (MTOK * 4)
#define SEL_BYTES  (MTOK * 4)
#define HIST_BYTES (NCODE * MTOK * 4)
#define SMEM_BYTES (SC_BYTES + BS_BYTES + RES_BYTES + C2S_BYTES + CAND_BYTES + \
                    R2S_BYTES + SEL_BYTES + HIST_BYTES)

__global__ __launch_bounds__(TPB, 1)
void rvq_kernel(const float* __restrict__ emb,
                const float* __restrict__ cb,
                float* __restrict__ out)
{
    extern __shared__ char smem[];
    __half* sc   = (__half*)smem;                        // [64][SCP]
    float*  bs   = (float*)(smem + SC_BYTES);            // [64][256]
    float*  res  = (float*)(smem + SC_BYTES + BS_BYTES); // [64][RPITCH]
    float*  c2s  = (float*)(smem + SC_BYTES + BS_BYTES + RES_BYTES);
    Cand*   cands= (Cand*)(smem + SC_BYTES + BS_BYTES + RES_BYTES + C2S_BYTES);
    float*  r2s  = (float*)((char*)cands + CAND_BYTES);
    int*    sel  = (int*)((char*)r2s + R2S_BYTES);
    int*    hist = (int*)((char*)sel + SEL_BYTES);       // [s][tok]

    const int tid  = threadIdx.x;
    const int w    = tid >> 5;
    const int lane = tid & 31;
    const int qr   = lane >> 2;     // 0..7
    const int qc   = lane & 3;      // 0..3
    const int mt   = w >> 1;        // m-tile 0..3
    const int nh   = w & 1;         // n half
    const int r0   = mt * 16 + qr;

    // ---- init: load embeddings into res smem ----
    {
        const int tok = tid & 63;
        const int ec  = tid >> 6;       // 0..3
        const int n   = blockIdx.x * MTOK + tok;
        const int b   = n >> 12;
        const int hw  = n & 4095;
        const float* ep = emb + (size_t)b * (EDIM * 4096) + hw;
#pragma unroll
        for (int j = 0; j < 16; j++) {
            int e = ec * 16 + j;
            res[tok * RPITCH + e] = ep[(size_t)e * 4096];
        }
    }
    __syncthreads();

#pragma unroll 1
    for (int s = 0; s < NCODE; s++) {
        // ---- A fragments for this warp's m-tile (tf32) ----
        unsigned a[32];
#pragma unroll
        for (int ks = 0; ks < 8; ks++) {
            int k0 = ks * 8;
            a[ks*4+0] = f2tf32(res[(r0    ) * RPITCH + k0     + qc]);
            a[ks*4+1] = f2tf32(res[(r0 + 8) * RPITCH + k0     + qc]);
            a[ks*4+2] = f2tf32(res[(r0    ) * RPITCH + k0 + 4 + qc]);
            a[ks*4+3] = f2tf32(res[(r0 + 8) * RPITCH + k0 + 4 + qc]);
        }
        // ---- exact r2 per token (sequential, e ascending) ----
        if (tid < MTOK) {
            const float* rr = res + tid * RPITCH;
            float r2 = 0.0f;
#pragma unroll
            for (int e = 0; e < EDIM; e++)
                r2 = __fadd_rn(r2, __fmul_rn(rr[e], rr[e]));
            r2s[tid] = r2;
        }

        // ---- score pass over K in 4 gtiles of 256 ----
#pragma unroll 1
        for (int gt = 0; gt < 4; gt++) {
            __syncthreads();
            // load B gtile (already tf32-truncated) [e][256]
            const float* gsrc = g_cbt + ((size_t)s * EDIM) * KCB + gt * GTW;
#pragma unroll
            for (int j = 0; j < 16; j++) {
                int idx = j * TPB + tid;
                int e   = idx >> 6;
                int c4  = idx & 63;
                float4 v = __ldg((const float4*)(gsrc + (size_t)e * KCB) + c4);
                *(float4*)(bs + e * GTW + c4 * 4) = v;
            }
            c2s[tid] = __ldg(g_cb2 + s * KCB + gt * GTW + tid);
            __syncthreads();

            // MMA: 16 n-tiles per warp, processed in pairs
#pragma unroll 1
            for (int nt = 0; nt < 16; nt += 2) {
                int n0 = nh * 128 + nt * 8;
                float c0=0.f,c1=0.f,c2=0.f,c3=0.f;
                float d0=0.f,d1=0.f,d2=0.f,d3=0.f;
                const float* bp0 = bs + n0 + qr;
                const float* bp1 = bp0 + 8;
#pragma unroll
                for (int ks = 0; ks < 8; ks++) {
                    unsigned bx0 = __float_as_uint(bp0[(ks*8     + qc) * GTW]);
                    unsigned bx1 = __float_as_uint(bp0[(ks*8 + 4 + qc) * GTW]);
                    unsigned by0 = __float_as_uint(bp1[(ks*8     + qc) * GTW]);
                    unsigned by1 = __float_as_uint(bp1[(ks*8 + 4 + qc) * GTW]);
                    mma_tf32(c0,c1,c2,c3, a[ks*4],a[ks*4+1],a[ks*4+2],a[ks*4+3], bx0,bx1);
                    mma_tf32(d0,d1,d2,d3, a[ks*4],a[ks*4+1],a[ks*4+2],a[ks*4+3], by0,by1);
                }
                // epilogue: t = cb2 - 2*dot -> fp16 scores
                int cc0 = n0 + 2*qc;
                int cc1 = cc0 + 8;
                float2 z0 = *(const float2*)(c2s + cc0);
                float2 z1 = *(const float2*)(c2s + cc1);
                __half2 h00 = __halves2half2(__float2half_rn(fmaf(-2.f,c0,z0.x)),
                                             __float2half_rn(fmaf(-2.f,c1,z0.y)));
                __half2 h01 = __halves2half2(__float2half_rn(fmaf(-2.f,c2,z0.x)),
                                             __float2half_rn(fmaf(-2.f,c3,z0.y)));
                __half2 h10 = __halves2half2(__float2half_rn(fmaf(-2.f,d0,z1.x)),
                                             __float2half_rn(fmaf(-2.f,d1,z1.y)));
                __half2 h11 = __halves2half2(__float2half_rn(fmaf(-2.f,d2,z1.x)),
                                             __float2half_rn(fmaf(-2.f,d3,z1.y)));
                int row0 = mt*16 + qr, row1 = row0 + 8;
                int g0 = gt * GTW + cc0;
                int g1 = gt * GTW + cc1;
                *(__half2*)(sc + row0 * SCP + g0) = h00;
                *(__half2*)(sc + row1 * SCP + g0) = h01;
                *(__half2*)(sc + row0 * SCP + g1) = h10;
                *(__half2*)(sc + row1 * SCP + g1) = h11;
            }
        }
        __syncthreads();   // scores complete

        // ---- per-warp verify: tokens w*8 .. w*8+7 ----
        Cand* cd = cands + w;
        if (lane == 0) cd->cnt = 0;
        __syncwarp();
        const int tbase = w * 8;
#pragma unroll 1
        for (int t8 = 0; t8 < 8; t8++) {
            const char* srow = (const char*)(sc + (tbase + t8) * SCP);
            uint4 v[4];
            float lmin = FLT_MAX;
#pragma unroll
            for (int jj = 0; jj < 4; jj++) {
                v[jj] = *(const uint4*)(srow + jj*512 + lane*16);
                float2 f0 = h2f(v[jj].x), f1 = h2f(v[jj].y);
                float2 f2 = h2f(v[jj].z), f3 = h2f(v[jj].w);
                lmin = fminf(lmin, fminf(fminf(fminf(f0.x,f0.y), fminf(f1.x,f1.y)),
                                         fminf(fminf(f2.x,f2.y), fminf(f3.x,f3.y))));
            }
#pragma unroll
            for (int off = 16; off; off >>= 1)
                lmin = fminf(lmin, __shfl_xor_sync(0xffffffffu, lmin, off));
            float thr = lmin + MARGIN;
#pragma unroll
            for (int jj = 0; jj < 4; jj++) {
                int kb = jj*256 + lane*8;
                unsigned uu[4] = {v[jj].x, v[jj].y, v[jj].z, v[jj].w};
#pragma unroll
                for (int m = 0; m < 4; m++) {
                    float2 f = h2f(uu[m]);
                    if (f.x <= thr) {
                        int p = atomicAdd(&cd->cnt, 1);
                        if (p < CAP) { cd->tok[p] = t8; cd->kk[p] = kb + 2*m; }
                    }
                    if (f.y <= thr) {
                        int p = atomicAdd(&cd->cnt, 1);
                        if (p < CAP) { cd->tok[p] = t8; cd->kk[p] = kb + 2*m + 1; }
                    }
                }
            }
        }
        __syncwarp();
        int ncand = min(cd->cnt, CAP);
        // parallel exact evaluation of all candidates (reference numerics)
        for (int base = 0; base < ncand; base += 32) {
            int i = base + lane;
            if (i < ncand) {
                int t8 = cd->tok[i];
                int k  = cd->kk[i];
                int tok = tbase + t8;
                const float4* q4 = (const float4*)(cb + ((size_t)(s * KCB + k)) * EDIM);
                float4 q[16];
#pragma unroll
                for (int ii = 0; ii < 16; ii++) q[ii] = __ldg(q4 + ii);
                const float* rr = res + tok * RPITCH;
                float dot = 0.0f;
#pragma unroll
                for (int ii = 0; ii < 16; ii++) {
                    dot = __fmaf_rn(rr[4*ii+0], q[ii].x, dot);
                    dot = __fmaf_rn(rr[4*ii+1], q[ii].y, dot);
                    dot = __fmaf_rn(rr[4*ii+2], q[ii].z, dot);
                    dot = __fmaf_rn(rr[4*ii+3], q[ii].w, dot);
                }
                float cb2 = __ldg(g_cb2 + s * KCB + k);
                cd->dd[i] = __fadd_rn(__fsub_rn(r2s[tok], __fmul_rn(2.0f, dot)), cb2);
            }
        }
        __syncwarp();
        // per-token select with first-index tie-break
        if (lane < 8) {
            float bd = FLT_MAX; int bk = KCB;
            for (int i = 0; i < ncand; i++) {
                if (cd->tok[i] == lane) {
                    float d = cd->dd[i]; int k = cd->kk[i];
                    if (d < bd || (d == bd && k < bk)) { bd = d; bk = k; }
                }
            }
            sel[tbase + lane] = bk;
        }
        __syncthreads();

        // ---- residual update (exact) ----
        {
            int tok  = tid >> 2;
            int part = tid & 3;
            int k    = sel[tok];
            const float4* qp = (const float4*)(cb + ((size_t)(s * KCB + k)) * EDIM) + part * 4;
            float* rr = res + tok * RPITCH + part * 16;
#pragma unroll
            for (int ii = 0; ii < 4; ii++) {
                float4 q  = __ldg(qp + ii);
                float4 rv = *(float4*)(rr + 4*ii);
                rv.x = __fsub_rn(rv.x, q.x);
                rv.y = __fsub_rn(rv.y, q.y);
                rv.z = __fsub_rn(rv.z, q.z);
                rv.w = __fsub_rn(rv.w, q.w);
                *(float4*)(rr + 4*ii) = rv;
            }
            if (part == 0) hist[s * MTOK + tok] = k;
        }
        __syncthreads();
    }

    // ---- final epilogue: quant = ((q0+q1)+q2)...+q7, exact order ----
    {
        const int tok = tid & 63;
        const int ec  = tid >> 6;
        const int e0  = ec * 16;
        const int n   = blockIdx.x * MTOK + tok;
        const int b   = n >> 12;
        const int hw  = n & 4095;

        float4 acc[4];
        {
            int k = hist[0 * MTOK + tok];
            const float4* qp = (const float4*)(cb + ((size_t)(0 * KCB + k)) * EDIM + e0);
#pragma unroll
            for (int ii = 0; ii < 4; ii++) acc[ii] = __ldg(qp + ii);
        }
#pragma unroll
        for (int s = 1; s < NCODE; s++) {
            int k = hist[s * MTOK + tok];
            const float4* qp = (const float4*)(cb + ((size_t)(s * KCB + k)) * EDIM + e0);
#pragma unroll
            for (int ii = 0; ii < 4; ii++) {
                float4 q = __ldg(qp + ii);
                acc[ii].x = __fadd_rn(acc[ii].x, q.x);
                acc[ii].y = __fadd_rn(acc[ii].y, q.y);
                acc[ii].z = __fadd_rn(acc[ii].z, q.z);
                acc[ii].w = __fadd_rn(acc[ii].w, q.w);
            }
        }
        float* op = out + (size_t)b * (EDIM * 4096) + hw;
#pragma unroll
        for (int ii = 0; ii < 4; ii++) {
            op[(size_t)(e0 + 4*ii + 0) * 4096] = acc[ii].x;
            op[(size_t)(e0 + 4*ii + 1) * 4096] = acc[ii].y;
            op[(size_t)(e0 + 4*ii + 2) * 4096] = acc[ii].z;
            op[(size_t)(e0 + 4*ii + 3) * 4096] = acc[ii].w;
        }
    }
}

extern "C" void kernel_launch(void* const* d_in, const int* in_sizes, int n_in,
                              void* d_out, int out_size)
{
    const float* emb = (const float*)d_in[0];   // [16,64,64,64]
    const float* cb  = (const float*)d_in[1];   // [8,1024,64]
    float* out = (float*)d_out;
    (void)in_sizes; (void)n_in; (void)out_size;

    cudaFuncSetAttribute(rvq_kernel, cudaFuncAttributeMaxDynamicSharedMemorySize,
                         SMEM_BYTES);

    cbt_kernel<<<dim3(32, 2, 8), dim3(32, 8)>>>(cb);
    cb2_kernel<<<(NCODE * KCB) / 256, 256>>>(cb);
    rvq_kernel<<<NTOK / MTOK, TPB, SMEM_BYTES>>>(emb, cb, out);
}

// round 4
// speedup vs baseline: 2.3711x; 1.6043x over previous
#include <cuda_runtime.h>
#include <cuda_fp16.h>
#include <cfloat>
#include <cstdint>

// ResidualVectorQuantizer, exact argmin via tf32-MMA prefilter + scalar verify.
// B=16,E=64,H=64,W=64 -> N=65536 tokens; K=1024, NC=8 stages.
//
// Exact reference numerics (validated rel_err==0 in rounds 1-3):
//   r2  = sequential sum of rounded squares of res (e ascending)
//   dot = sequential fused-FMA over e ascending
//   d   = fl(fl(r2 - fl(2*dot)) + cb2), argmin first-index tie-break
//   res -= q elementwise rounded; quant = ((q0+q1)+...)+q7
// MMA computes approximate scores t~ = cb2 - 2*dot~ (tf32); every k with
// t~ <= min + MARGIN is re-verified exactly (MARGIN >> max approx error).
//
// R4 changes vs R3 (perf only, numerics identical):
//  - each warp owns a 32-wide n-slice and ALL 4 m-tiles (A in 128 regs):
//    4 B-LDS now feed 8 MMAs (was 4 LDS : 2 MMAs)  -> 4x fewer LDS
//  - B tile pitch 256 -> 264 floats: bank = 8*qc + qr, conflict-free
//    (was 4-way conflicted)                          -> 4x cheaper LDS

#define NTOK   65536
#define EDIM   64
#define KCB    1024
#define NCODE  8
#define MTOK   64          // tokens per CTA
#define TPB    256
#define GTW    256         // codebook k-gtile width
#define BPITCH 264         // padded B tile pitch (floats): conflict-free
#define RPITCH 68          // res row pitch (floats)
#define SCP    1032        // score row pitch (halves)
#define CAP    64
#define MARGIN 1e-3f

__device__ float g_cbt[NCODE * EDIM * KCB];  // tf32-truncated, [s][e][k]
__device__ float g_cb2[NCODE * KCB];         // exact ||cb||^2

__device__ __forceinline__ unsigned f2tf32(float x) {
    unsigned r;
    asm("cvt.rna.tf32.f32 %0, %1;" : "=r"(r) : "f"(x));
    return r;
}

__device__ __forceinline__ float2 h2f(unsigned u) {
    __half2 h = *reinterpret_cast<__half2*>(&u);
    return __half22float2(h);
}

__device__ __forceinline__ void mma_tf32(float& c0, float& c1, float& c2, float& c3,
                                         unsigned a0, unsigned a1, unsigned a2, unsigned a3,
                                         unsigned b0, unsigned b1) {
    asm volatile(
        "mma.sync.aligned.m16n8k8.row.col.f32.tf32.tf32.f32 "
        "{%0,%1,%2,%3}, {%4,%5,%6,%7}, {%8,%9}, {%0,%1,%2,%3};\n"
        : "+f"(c0), "+f"(c1), "+f"(c2), "+f"(c3)
        : "r"(a0), "r"(a1), "r"(a2), "r"(a3), "r"(b0), "r"(b1));
}

// ---- precompute: exact cb2 ----
__global__ void cb2_kernel(const float* __restrict__ cb)
{
    const int i = blockIdx.x * blockDim.x + threadIdx.x;   // 0..8191
    const float* row = cb + (size_t)i * EDIM;
    float c2 = 0.0f;
#pragma unroll
    for (int e = 0; e < EDIM; e++)
        c2 = __fadd_rn(c2, __fmul_rn(row[e], row[e]));
    g_cb2[i] = c2;
}

// ---- precompute: transpose + tf32-truncate codebook to [s][e][k] ----
__global__ void cbt_kernel(const float* __restrict__ cb)
{
    __shared__ float tile[32][33];
    const int s  = blockIdx.z;
    const int n0 = blockIdx.x * 32;
    const int e0 = blockIdx.y * 32;
    const int tx = threadIdx.x, ty = threadIdx.y;
#pragma unroll
    for (int i = 0; i < 32; i += 8)
        tile[ty + i][tx] = cb[((size_t)s * KCB + (n0 + ty + i)) * EDIM + e0 + tx];
    __syncthreads();
#pragma unroll
    for (int i = 0; i < 32; i += 8) {
        unsigned t = f2tf32(tile[tx][ty + i]);
        g_cbt[((size_t)s * EDIM + (e0 + ty + i)) * KCB + n0 + tx] = __uint_as_float(t);
    }
}

struct Cand {
    int   cnt;
    int   pad[3];
    int   tok[CAP];
    int   kk[CAP];
    float dd[CAP];
};

// smem segment sizes (bytes)
#define SC_BYTES   (MTOK * SCP * 2)          // 132096
#define BS_BYTES   (EDIM * BPITCH * 4)       // 67584
#define RES_BYTES  (MTOK * RPITCH * 4)       // 17408
#define C2S_BYTES  (GTW * 4)                 // 1024
#define CAND_BYTES (8 * (int)sizeof(Cand))   // 6272
#define R2S_BYTES  (MTOK * 4)
#define SEL_BYTES  (MTOK * 4)
#define HIST_BYTES (NCODE * MTOK * 4)
#define SMEM_BYTES (SC_BYTES + BS_BYTES + RES_BYTES + C2S_BYTES + CAND_BYTES + \
                    R2S_BYTES + SEL_BYTES + HIST_BYTES)

__global__ __launch_bounds__(TPB, 1)
void rvq_kernel(const float* __restrict__ emb,
                const float* __restrict__ cb,
                float* __restrict__ out)
{
    extern __shared__ char smem[];
    __half* sc   = (__half*)smem;                        // [64][SCP]
    float*  bs   = (float*)(smem + SC_BYTES);            // [64][BPITCH]
    float*  res  = (float*)(smem + SC_BYTES + BS_BYTES); // [64][RPITCH]
    float*  c2s  = (float*)(smem + SC_BYTES + BS_BYTES + RES_BYTES);
    Cand*   cands= (Cand*)(smem + SC_BYTES + BS_BYTES + RES_BYTES + C2S_BYTES);
    float*  r2s  = (float*)((char*)cands + CAND_BYTES);
    int*    sel  = (int*)((char*)r2s + R2S_BYTES);
    int*    hist = (int*)((char*)sel + SEL_BYTES);       // [s][tok]

    const int tid  = threadIdx.x;
    const int w    = tid >> 5;
    const int lane = tid & 31;
    const int qr   = lane >> 2;     // 0..7
    const int qc   = lane & 3;      // 0..3

    // ---- init: load embeddings into res smem ----
    {
        const int tok = tid & 63;
        const int ec  = tid >> 6;       // 0..3
        const int n   = blockIdx.x * MTOK + tok;
        const int b   = n >> 12;
        const int hw  = n & 4095;
        const float* ep = emb + (size_t)b * (EDIM * 4096) + hw;
#pragma unroll
        for (int j = 0; j < 16; j++) {
            int e = ec * 16 + j;
            res[tok * RPITCH + e] = ep[(size_t)e * 4096];
        }
    }
    __syncthreads();

#pragma unroll 1
    for (int s = 0; s < NCODE; s++) {
        // ---- A fragments: all 4 m-tiles (tf32), 128 regs ----
        unsigned a[4][32];
#pragma unroll
        for (int mt = 0; mt < 4; mt++) {
            int r0 = mt * 16 + qr;
#pragma unroll
            for (int ks = 0; ks < 8; ks++) {
                int k0 = ks * 8;
                a[mt][ks*4+0] = f2tf32(res[(r0    ) * RPITCH + k0     + qc]);
                a[mt][ks*4+1] = f2tf32(res[(r0 + 8) * RPITCH + k0     + qc]);
                a[mt][ks*4+2] = f2tf32(res[(r0    ) * RPITCH + k0 + 4 + qc]);
                a[mt][ks*4+3] = f2tf32(res[(r0 + 8) * RPITCH + k0 + 4 + qc]);
            }
        }
        // ---- exact r2 per token (sequential, e ascending) ----
        if (tid < MTOK) {
            const float* rr = res + tid * RPITCH;
            float r2 = 0.0f;
#pragma unroll
            for (int e = 0; e < EDIM; e++)
                r2 = __fadd_rn(r2, __fmul_rn(rr[e], rr[e]));
            r2s[tid] = r2;
        }

        // ---- score pass over K in 4 gtiles of 256 ----
#pragma unroll 1
        for (int gt = 0; gt < 4; gt++) {
            __syncthreads();
            // load B gtile (already tf32-truncated) into [e][BPITCH]
            const float* gsrc = g_cbt + ((size_t)s * EDIM) * KCB + gt * GTW;
#pragma unroll
            for (int j = 0; j < 16; j++) {
                int idx = j * TPB + tid;
                int e   = idx >> 6;
                int c4  = idx & 63;
                float4 v = __ldg((const float4*)(gsrc + (size_t)e * KCB) + c4);
                *(float4*)(bs + e * BPITCH + c4 * 4) = v;
            }
            c2s[tid] = __ldg(g_cb2 + s * KCB + gt * GTW + tid);
            __syncthreads();

            // this warp's 32-wide n-slice, two 16-wide passes
            const int nbase = w * 32;
#pragma unroll 1
            for (int np = 0; np < 2; np++) {
                const int n0 = nbase + np * 16;
                float acc[4][8];
#pragma unroll
                for (int mt = 0; mt < 4; mt++)
#pragma unroll
                    for (int j = 0; j < 8; j++) acc[mt][j] = 0.0f;

                const float* bp = bs + n0 + qr;
#pragma unroll
                for (int ks = 0; ks < 8; ks++) {
                    // conflict-free: bank = 8*qc + qr
                    unsigned bx0 = __float_as_uint(bp[(ks*8     + qc) * BPITCH]);
                    unsigned bx1 = __float_as_uint(bp[(ks*8 + 4 + qc) * BPITCH]);
                    unsigned by0 = __float_as_uint(bp[(ks*8     + qc) * BPITCH + 8]);
                    unsigned by1 = __float_as_uint(bp[(ks*8 + 4 + qc) * BPITCH + 8]);
#pragma unroll
                    for (int mt = 0; mt < 4; mt++) {
                        mma_tf32(acc[mt][0], acc[mt][1], acc[mt][2], acc[mt][3],
                                 a[mt][ks*4], a[mt][ks*4+1], a[mt][ks*4+2], a[mt][ks*4+3],
                                 bx0, bx1);
                        mma_tf32(acc[mt][4], acc[mt][5], acc[mt][6], acc[mt][7],
                                 a[mt][ks*4], a[mt][ks*4+1], a[mt][ks*4+2], a[mt][ks*4+3],
                                 by0, by1);
                    }
                }
                // epilogue: t = cb2 - 2*dot -> fp16 scores
                const int cc0 = n0 + 2*qc;
                const int cc1 = cc0 + 8;
                float2 z0 = *(const float2*)(c2s + cc0);
                float2 z1 = *(const float2*)(c2s + cc1);
                const int g0 = gt * GTW + cc0;
                const int g1 = gt * GTW + cc1;
#pragma unroll
                for (int mt = 0; mt < 4; mt++) {
                    int row0 = mt * 16 + qr, row1 = row0 + 8;
                    __half2 h00 = __halves2half2(__float2half_rn(fmaf(-2.f, acc[mt][0], z0.x)),
                                                 __float2half_rn(fmaf(-2.f, acc[mt][1], z0.y)));
                    __half2 h01 = __halves2half2(__float2half_rn(fmaf(-2.f, acc[mt][2], z0.x)),
                                                 __float2half_rn(fmaf(-2.f, acc[mt][3], z0.y)));
                    __half2 h10 = __halves2half2(__float2half_rn(fmaf(-2.f, acc[mt][4], z1.x)),
                                                 __float2half_rn(fmaf(-2.f, acc[mt][5], z1.y)));
                    __half2 h11 = __halves2half2(__float2half_rn(fmaf(-2.f, acc[mt][6], z1.x)),
                                                 __float2half_rn(fmaf(-2.f, acc[mt][7], z1.y)));
                    *(__half2*)(sc + row0 * SCP + g0) = h00;
                    *(__half2*)(sc + row1 * SCP + g0) = h01;
                    *(__half2*)(sc + row0 * SCP + g1) = h10;
                    *(__half2*)(sc + row1 * SCP + g1) = h11;
                }
            }
        }
        __syncthreads();   // scores complete

        // ---- per-warp verify: tokens w*8 .. w*8+7 ----
        Cand* cd = cands + w;
        if (lane == 0) cd->cnt = 0;
        __syncwarp();
        const int tbase = w * 8;
#pragma unroll 1
        for (int t8 = 0; t8 < 8; t8++) {
            const char* srow = (const char*)(sc + (tbase + t8) * SCP);
            uint4 v[4];
            float lmin = FLT_MAX;
#pragma unroll
            for (int jj = 0; jj < 4; jj++) {
                v[jj] = *(const uint4*)(srow + jj*512 + lane*16);
                float2 f0 = h2f(v[jj].x), f1 = h2f(v[jj].y);
                float2 f2 = h2f(v[jj].z), f3 = h2f(v[jj].w);
                lmin = fminf(lmin, fminf(fminf(fminf(f0.x,f0.y), fminf(f1.x,f1.y)),
                                         fminf(fminf(f2.x,f2.y), fminf(f3.x,f3.y))));
            }
#pragma unroll
            for (int off = 16; off; off >>= 1)
                lmin = fminf(lmin, __shfl_xor_sync(0xffffffffu, lmin, off));
            float thr = lmin + MARGIN;
#pragma unroll
            for (int jj = 0; jj < 4; jj++) {
                int kb = jj*256 + lane*8;
                unsigned uu[4] = {v[jj].x, v[jj].y, v[jj].z, v[jj].w};
#pragma unroll
                for (int m = 0; m < 4; m++) {
                    float2 f = h2f(uu[m]);
                    if (f.x <= thr) {
                        int p = atomicAdd(&cd->cnt, 1);
                        if (p < CAP) { cd->tok[p] = t8; cd->kk[p] = kb + 2*m; }
                    }
                    if (f.y <= thr) {
                        int p = atomicAdd(&cd->cnt, 1);
                        if (p < CAP) { cd->tok[p] = t8; cd->kk[p] = kb + 2*m + 1; }
                    }
                }
            }
        }
        __syncwarp();
        int ncand = min(cd->cnt, CAP);
        // parallel exact evaluation of all candidates (reference numerics)
        for (int base = 0; base < ncand; base += 32) {
            int i = base + lane;
            if (i < ncand) {
                int t8 = cd->tok[i];
                int k  = cd->kk[i];
                int tok = tbase + t8;
                const float4* q4 = (const float4*)(cb + ((size_t)(s * KCB + k)) * EDIM);
                float4 q[16];
#pragma unroll
                for (int ii = 0; ii < 16; ii++) q[ii] = __ldg(q4 + ii);
                const float* rr = res + tok * RPITCH;
                float dot = 0.0f;
#pragma unroll
                for (int ii = 0; ii < 16; ii++) {
                    dot = __fmaf_rn(rr[4*ii+0], q[ii].x, dot);
                    dot = __fmaf_rn(rr[4*ii+1], q[ii].y, dot);
                    dot = __fmaf_rn(rr[4*ii+2], q[ii].z, dot);
                    dot = __fmaf_rn(rr[4*ii+3], q[ii].w, dot);
                }
                float cb2 = __ldg(g_cb2 + s * KCB + k);
                cd->dd[i] = __fadd_rn(__fsub_rn(r2s[tok], __fmul_rn(2.0f, dot)), cb2);
            }
        }
        __syncwarp();
        // per-token select with first-index tie-break
        if (lane < 8) {
            float bd = FLT_MAX; int bk = KCB;
            for (int i = 0; i < ncand; i++) {
                if (cd->tok[i] == lane) {
                    float d = cd->dd[i]; int k = cd->kk[i];
                    if (d < bd || (d == bd && k < bk)) { bd = d; bk = k; }
                }
            }
            sel[tbase + lane] = bk;
        }
        __syncthreads();

        // ---- residual update (exact) ----
        {
            int tok  = tid >> 2;
            int part = tid & 3;
            int k    = sel[tok];
            const float4* qp = (const float4*)(cb + ((size_t)(s * KCB + k)) * EDIM) + part * 4;
            float* rr = res + tok * RPITCH + part * 16;
#pragma unroll
            for (int ii = 0; ii < 4; ii++) {
                float4 q  = __ldg(qp + ii);
                float4 rv = *(float4*)(rr + 4*ii);
                rv.x = __fsub_rn(rv.x, q.x);
                rv.y = __fsub_rn(rv.y, q.y);
                rv.z = __fsub_rn(rv.z, q.z);
                rv.w = __fsub_rn(rv.w, q.w);
                *(float4*)(rr + 4*ii) = rv;
            }
            if (part == 0) hist[s * MTOK + tok] = k;
        }
        __syncthreads();
    }

    // ---- final epilogue: quant = ((q0+q1)+q2)...+q7, exact order ----
    {
        const int tok = tid & 63;
        const int ec  = tid >> 6;
        const int e0  = ec * 16;
        const int n   = blockIdx.x * MTOK + tok;
        const int b   = n >> 12;
        const int hw  = n & 4095;

        float4 acc[4];
        {
            int k = hist[0 * MTOK + tok];
            const float4* qp = (const float4*)(cb + ((size_t)(0 * KCB + k)) * EDIM + e0);
#pragma unroll
            for (int ii = 0; ii < 4; ii++) acc[ii] = __ldg(qp + ii);
        }
#pragma unroll
        for (int s = 1; s < NCODE; s++) {
            int k = hist[s * MTOK + tok];
            const float4* qp = (const float4*)(cb + ((size_t)(s * KCB + k)) * EDIM + e0);
#pragma unroll
            for (int ii = 0; ii < 4; ii++) {
                float4 q = __ldg(qp + ii);
                acc[ii].x = __fadd_rn(acc[ii].x, q.x);
                acc[ii].y = __fadd_rn(acc[ii].y, q.y);
                acc[ii].z = __fadd_rn(acc[ii].z, q.z);
                acc[ii].w = __fadd_rn(acc[ii].w, q.w);
            }
        }
        float* op = out + (size_t)b * (EDIM * 4096) + hw;
#pragma unroll
        for (int ii = 0; ii < 4; ii++) {
            op[(size_t)(e0 + 4*ii + 0) * 4096] = acc[ii].x;
            op[(size_t)(e0 + 4*ii + 1) * 4096] = acc[ii].y;
            op[(size_t)(e0 + 4*ii + 2) * 4096] = acc[ii].z;
            op[(size_t)(e0 + 4*ii + 3) * 4096] = acc[ii].w;
        }
    }
}

extern "C" void kernel_launch(void* const* d_in, const int* in_sizes, int n_in,
                              void* d_out, int out_size)
{
    const float* emb = (const float*)d_in[0];   // [16,64,64,64]
    const float* cb  = (const float*)d_in[1];   // [8,1024,64]
    float* out = (float*)d_out;
    (void)in_sizes; (void)n_in; (void)out_size;

    cudaFuncSetAttribute(rvq_kernel, cudaFuncAttributeMaxDynamicSharedMemorySize,
                         SMEM_BYTES);

    cbt_kernel<<<dim3(32, 2, 8), dim3(32, 8)>>>(cb);
    cb2_kernel<<<(NCODE * KCB) / 256, 256>>>(cb);
    rvq_kernel<<<NTOK / MTOK, TPB, SMEM_BYTES>>>(emb, cb, out);
}

// round 5
// speedup vs baseline: 2.9497x; 1.2440x over previous
#include <cuda_runtime.h>
#include <cuda_fp16.h>
#include <cfloat>
#include <cstdint>

// ResidualVectorQuantizer, exact argmin via tf32-MMA prefilter + scalar verify.
// B=16,E=64,H=64,W=64 -> N=65536 tokens; K=1024, NC=8 stages.
//
// Exact reference numerics (validated rel_err==0 in rounds 1-4):
//   r2  = sequential sum of rounded squares of res (e ascending)
//   dot = sequential fused-FMA over e ascending
//   d   = fl(fl(r2 - fl(2*dot)) + cb2), argmin first-index tie-break
//   res -= q elementwise rounded; quant = ((q0+q1)+...)+q7
// MMA computes approximate scores t~ = cb2 - 2*dot~ (tf32, fp16-stored);
// every k with t~ <= min + MARGIN is re-verified exactly.
//
// R5 changes vs R4 (perf only):
//  - 512 threads (16 warps = 8 n-slices x 2 m-halves): 4 warps/SMSP to hide
//    LDS/HMMA latency (was 2). A frags 64 regs, <=128 regs/thread.
//  - scan uses __hmin2 trees + block-min early-out (no fp32 unpack of all
//    scores) -> ~6x fewer scan ops. Exact: score<=thr => block min<=thr.

#define NTOK   65536
#define EDIM   64
#define KCB    1024
#define NCODE  8
#define MTOK   64          // tokens per CTA
#define TPB    512
#define NWARP  16
#define GTW    256         // codebook k-gtile width
#define BPITCH 264         // padded B tile pitch (floats): conflict-free
#define RPITCH 68          // res row pitch (floats)
#define SCP    1032        // score row pitch (halves)
#define CAP    48
#define MARGIN 1e-3f

__device__ float g_cbt[NCODE * EDIM * KCB];  // tf32-truncated, [s][e][k]
__device__ float g_cb2[NCODE * KCB];         // exact ||cb||^2

__device__ __forceinline__ unsigned f2tf32(float x) {
    unsigned r;
    asm("cvt.rna.tf32.f32 %0, %1;" : "=r"(r) : "f"(x));
    return r;
}

__device__ __forceinline__ __half2 u2h2(unsigned u) {
    return *reinterpret_cast<__half2*>(&u);
}

__device__ __forceinline__ void mma_tf32(float& c0, float& c1, float& c2, float& c3,
                                         unsigned a0, unsigned a1, unsigned a2, unsigned a3,
                                         unsigned b0, unsigned b1) {
    asm volatile(
        "mma.sync.aligned.m16n8k8.row.col.f32.tf32.tf32.f32 "
        "{%0,%1,%2,%3}, {%4,%5,%6,%7}, {%8,%9}, {%0,%1,%2,%3};\n"
        : "+f"(c0), "+f"(c1), "+f"(c2), "+f"(c3)
        : "r"(a0), "r"(a1), "r"(a2), "r"(a3), "r"(b0), "r"(b1));
}

// ---- precompute: exact cb2 ----
__global__ void cb2_kernel(const float* __restrict__ cb)
{
    const int i = blockIdx.x * blockDim.x + threadIdx.x;   // 0..8191
    const float* row = cb + (size_t)i * EDIM;
    float c2 = 0.0f;
#pragma unroll
    for (int e = 0; e < EDIM; e++)
        c2 = __fadd_rn(c2, __fmul_rn(row[e], row[e]));
    g_cb2[i] = c2;
}

// ---- precompute: transpose + tf32-truncate codebook to [s][e][k] ----
__global__ void cbt_kernel(const float* __restrict__ cb)
{
    __shared__ float tile[32][33];
    const int s  = blockIdx.z;
    const int n0 = blockIdx.x * 32;
    const int e0 = blockIdx.y * 32;
    const int tx = threadIdx.x, ty = threadIdx.y;
#pragma unroll
    for (int i = 0; i < 32; i += 8)
        tile[ty + i][tx] = cb[((size_t)s * KCB + (n0 + ty + i)) * EDIM + e0 + tx];
    __syncthreads();
#pragma unroll
    for (int i = 0; i < 32; i += 8) {
        unsigned t = f2tf32(tile[tx][ty + i]);
        g_cbt[((size_t)s * EDIM + (e0 + ty + i)) * KCB + n0 + tx] = __uint_as_float(t);
    }
}

struct Cand {
    int   cnt;
    int   pad[3];
    int   tok[CAP];
    int   kk[CAP];
    float dd[CAP];
};

// smem segment sizes (bytes)
#define SC_BYTES   (MTOK * SCP * 2)            // 132096
#define BS_BYTES   (EDIM * BPITCH * 4)         // 67584
#define RES_BYTES  (MTOK * RPITCH * 4)         // 17408
#define C2S_BYTES  (GTW * 4)                   // 1024
#define CAND_BYTES (NWARP * (int)sizeof(Cand)) // 16*592 = 9472
#define R2S_BYTES  (MTOK * 4)
#define SEL_BYTES  (MTOK * 4)
#define HIST_BYTES (NCODE * MTOK * 4)
#define SMEM_BYTES (SC_BYTES + BS_BYTES + RES_BYTES + C2S_BYTES + CAND_BYTES + \
                    R2S_BYTES + SEL_BYTES + HIST_BYTES)

__global__ __launch_bounds__(TPB, 1)
void rvq_kernel(const float* __restrict__ emb,
                const float* __restrict__ cb,
                float* __restrict__ out)
{
    extern __shared__ char smem[];
    __half* sc   = (__half*)smem;                        // [64][SCP]
    float*  bs   = (float*)(smem + SC_BYTES);            // [64][BPITCH]
    float*  res  = (float*)(smem + SC_BYTES + BS_BYTES); // [64][RPITCH]
    float*  c2s  = (float*)(smem + SC_BYTES + BS_BYTES + RES_BYTES);
    Cand*   cands= (Cand*)(smem + SC_BYTES + BS_BYTES + RES_BYTES + C2S_BYTES);
    float*  r2s  = (float*)((char*)cands + CAND_BYTES);
    int*    sel  = (int*)((char*)r2s + R2S_BYTES);
    int*    hist = (int*)((char*)sel + SEL_BYTES);       // [s][tok]

    const int tid  = threadIdx.x;
    const int w    = tid >> 5;      // 0..15
    const int lane = tid & 31;
    const int qr   = lane >> 2;     // 0..7
    const int qc   = lane & 3;      // 0..3
    const int nw   = w & 7;         // n-slice (32 wide)
    const int mh   = w >> 3;        // m-half: m-tiles {2mh, 2mh+1}

    // ---- init: load embeddings into res smem ----
    {
        const int tok = tid & 63;
        const int ec  = tid >> 6;       // 0..7
        const int n   = blockIdx.x * MTOK + tok;
        const int b   = n >> 12;
        const int hw  = n & 4095;
        const float* ep = emb + (size_t)b * (EDIM * 4096) + hw;
#pragma unroll
        for (int j = 0; j < 8; j++) {
            int e = ec * 8 + j;
            res[tok * RPITCH + e] = ep[(size_t)e * 4096];
        }
    }
    __syncthreads();

#pragma unroll 1
    for (int s = 0; s < NCODE; s++) {
        // ---- A fragments: this warp's 2 m-tiles (tf32), 64 regs ----
        unsigned a[2][32];
#pragma unroll
        for (int mtl = 0; mtl < 2; mtl++) {
            int r0 = (mh * 2 + mtl) * 16 + qr;
#pragma unroll
            for (int ks = 0; ks < 8; ks++) {
                int k0 = ks * 8;
                a[mtl][ks*4+0] = f2tf32(res[(r0    ) * RPITCH + k0     + qc]);
                a[mtl][ks*4+1] = f2tf32(res[(r0 + 8) * RPITCH + k0     + qc]);
                a[mtl][ks*4+2] = f2tf32(res[(r0    ) * RPITCH + k0 + 4 + qc]);
                a[mtl][ks*4+3] = f2tf32(res[(r0 + 8) * RPITCH + k0 + 4 + qc]);
            }
        }
        // ---- exact r2 per token (sequential, e ascending) ----
        if (tid < MTOK) {
            const float* rr = res + tid * RPITCH;
            float r2 = 0.0f;
#pragma unroll
            for (int e = 0; e < EDIM; e++)
                r2 = __fadd_rn(r2, __fmul_rn(rr[e], rr[e]));
            r2s[tid] = r2;
        }

        // ---- score pass over K in 4 gtiles of 256 ----
#pragma unroll 1
        for (int gt = 0; gt < 4; gt++) {
            __syncthreads();
            // load B gtile (already tf32-truncated) into [e][BPITCH]
            const float* gsrc = g_cbt + ((size_t)s * EDIM) * KCB + gt * GTW;
#pragma unroll
            for (int j = 0; j < 8; j++) {
                int idx = j * TPB + tid;
                int e   = idx >> 6;
                int c4  = idx & 63;
                float4 v = __ldg((const float4*)(gsrc + (size_t)e * KCB) + c4);
                *(float4*)(bs + e * BPITCH + c4 * 4) = v;
            }
            if (tid < GTW)
                c2s[tid] = __ldg(g_cb2 + s * KCB + gt * GTW + tid);
            __syncthreads();

            // this warp's 32-wide n-slice, two 16-wide passes, 2 m-tiles
            const int nbase = nw * 32;
#pragma unroll 1
            for (int np = 0; np < 2; np++) {
                const int n0 = nbase + np * 16;
                float acc[2][8];
#pragma unroll
                for (int mtl = 0; mtl < 2; mtl++)
#pragma unroll
                    for (int j = 0; j < 8; j++) acc[mtl][j] = 0.0f;

                const float* bp = bs + n0 + qr;
#pragma unroll
                for (int ks = 0; ks < 8; ks++) {
                    // conflict-free: bank = 8*qc + qr
                    unsigned bx0 = __float_as_uint(bp[(ks*8     + qc) * BPITCH]);
                    unsigned bx1 = __float_as_uint(bp[(ks*8 + 4 + qc) * BPITCH]);
                    unsigned by0 = __float_as_uint(bp[(ks*8     + qc) * BPITCH + 8]);
                    unsigned by1 = __float_as_uint(bp[(ks*8 + 4 + qc) * BPITCH + 8]);
#pragma unroll
                    for (int mtl = 0; mtl < 2; mtl++) {
                        mma_tf32(acc[mtl][0], acc[mtl][1], acc[mtl][2], acc[mtl][3],
                                 a[mtl][ks*4], a[mtl][ks*4+1], a[mtl][ks*4+2], a[mtl][ks*4+3],
                                 bx0, bx1);
                        mma_tf32(acc[mtl][4], acc[mtl][5], acc[mtl][6], acc[mtl][7],
                                 a[mtl][ks*4], a[mtl][ks*4+1], a[mtl][ks*4+2], a[mtl][ks*4+3],
                                 by0, by1);
                    }
                }
                // epilogue: t = cb2 - 2*dot -> fp16 scores
                const int cc0 = n0 + 2*qc;
                const int cc1 = cc0 + 8;
                float2 z0 = *(const float2*)(c2s + cc0);
                float2 z1 = *(const float2*)(c2s + cc1);
                const int g0 = gt * GTW + cc0;
                const int g1 = gt * GTW + cc1;
#pragma unroll
                for (int mtl = 0; mtl < 2; mtl++) {
                    int row0 = (mh * 2 + mtl) * 16 + qr, row1 = row0 + 8;
                    __half2 h00 = __halves2half2(__float2half_rn(fmaf(-2.f, acc[mtl][0], z0.x)),
                                                 __float2half_rn(fmaf(-2.f, acc[mtl][1], z0.y)));
                    __half2 h01 = __halves2half2(__float2half_rn(fmaf(-2.f, acc[mtl][2], z0.x)),
                                                 __float2half_rn(fmaf(-2.f, acc[mtl][3], z0.y)));
                    __half2 h10 = __halves2half2(__float2half_rn(fmaf(-2.f, acc[mtl][4], z1.x)),
                                                 __float2half_rn(fmaf(-2.f, acc[mtl][5], z1.y)));
                    __half2 h11 = __halves2half2(__float2half_rn(fmaf(-2.f, acc[mtl][6], z1.x)),
                                                 __float2half_rn(fmaf(-2.f, acc[mtl][7], z1.y)));
                    *(__half2*)(sc + row0 * SCP + g0) = h00;
                    *(__half2*)(sc + row1 * SCP + g0) = h01;
                    *(__half2*)(sc + row0 * SCP + g1) = h10;
                    *(__half2*)(sc + row1 * SCP + g1) = h11;
                }
            }
        }
        __syncthreads();   // scores complete

        // ---- per-warp verify: tokens w*4 .. w*4+3 ----
        Cand* cd = cands + w;
        if (lane == 0) cd->cnt = 0;
        __syncwarp();
        const int tbase = w * 4;
#pragma unroll 1
        for (int t4 = 0; t4 < 4; t4++) {
            const char* srow = (const char*)(sc + (tbase + t4) * SCP);
            uint4 v[4];
            __half2 bmin[4];                 // per-uint4 block min (8 halves)
            __half2 m = __halves2half2(__half(65504.f), __half(65504.f));
#pragma unroll
            for (int jj = 0; jj < 4; jj++) {
                v[jj] = *(const uint4*)(srow + jj*512 + lane*16);
                __half2 m0 = __hmin2(u2h2(v[jj].x), u2h2(v[jj].y));
                __half2 m1 = __hmin2(u2h2(v[jj].z), u2h2(v[jj].w));
                bmin[jj] = __hmin2(m0, m1);
                m = __hmin2(m, bmin[jj]);
            }
            float lmin = __half2float(__hmin(__low2half(m), __high2half(m)));
#pragma unroll
            for (int off = 16; off; off >>= 1)
                lmin = fminf(lmin, __shfl_xor_sync(0xffffffffu, lmin, off));
            const float thr = lmin + MARGIN;
#pragma unroll
            for (int jj = 0; jj < 4; jj++) {
                float bm = __half2float(__hmin(__low2half(bmin[jj]), __high2half(bmin[jj])));
                if (bm <= thr) {           // rare: fine-scan this 8-wide block
                    int kb = jj*256 + lane*8;
                    unsigned uu[4] = {v[jj].x, v[jj].y, v[jj].z, v[jj].w};
#pragma unroll
                    for (int mm = 0; mm < 4; mm++) {
                        __half2 h = u2h2(uu[mm]);
                        if (__half2float(__low2half(h)) <= thr) {
                            int p = atomicAdd(&cd->cnt, 1);
                            if (p < CAP) { cd->tok[p] = t4; cd->kk[p] = kb + 2*mm; }
                        }
                        if (__half2float(__high2half(h)) <= thr) {
                            int p = atomicAdd(&cd->cnt, 1);
                            if (p < CAP) { cd->tok[p] = t4; cd->kk[p] = kb + 2*mm + 1; }
                        }
                    }
                }
            }
        }
        __syncwarp();
        int ncand = min(cd->cnt, CAP);
        // parallel exact evaluation of all candidates (reference numerics)
        for (int base = 0; base < ncand; base += 32) {
            int i = base + lane;
            if (i < ncand) {
                int t4 = cd->tok[i];
                int k  = cd->kk[i];
                int tok = tbase + t4;
                const float4* q4 = (const float4*)(cb + ((size_t)(s * KCB + k)) * EDIM);
                float4 q[16];
#pragma unroll
                for (int ii = 0; ii < 16; ii++) q[ii] = __ldg(q4 + ii);
                const float* rr = res + tok * RPITCH;
                float dot = 0.0f;
#pragma unroll
                for (int ii = 0; ii < 16; ii++) {
                    dot = __fmaf_rn(rr[4*ii+0], q[ii].x, dot);
                    dot = __fmaf_rn(rr[4*ii+1], q[ii].y, dot);
                    dot = __fmaf_rn(rr[4*ii+2], q[ii].z, dot);
                    dot = __fmaf_rn(rr[4*ii+3], q[ii].w, dot);
                }
                float cb2 = __ldg(g_cb2 + s * KCB + k);
                cd->dd[i] = __fadd_rn(__fsub_rn(r2s[tok], __fmul_rn(2.0f, dot)), cb2);
            }
        }
        __syncwarp();
        // per-token select with first-index tie-break
        if (lane < 4) {
            float bd = FLT_MAX; int bk = KCB;
            for (int i = 0; i < ncand; i++) {
                if (cd->tok[i] == lane) {
                    float d = cd->dd[i]; int k = cd->kk[i];
                    if (d < bd || (d == bd && k < bk)) { bd = d; bk = k; }
                }
            }
            sel[tbase + lane] = bk;
        }
        __syncthreads();

        // ---- residual update (exact) ----
        {
            int tok  = tid >> 3;           // 0..63
            int part = tid & 7;            // 0..7, 8 floats each
            int k    = sel[tok];
            const float4* qp = (const float4*)(cb + ((size_t)(s * KCB + k)) * EDIM) + part * 2;
            float* rr = res + tok * RPITCH + part * 8;
#pragma unroll
            for (int ii = 0; ii < 2; ii++) {
                float4 q  = __ldg(qp + ii);
                float4 rv = *(float4*)(rr + 4*ii);
                rv.x = __fsub_rn(rv.x, q.x);
                rv.y = __fsub_rn(rv.y, q.y);
                rv.z = __fsub_rn(rv.z, q.z);
                rv.w = __fsub_rn(rv.w, q.w);
                *(float4*)(rr + 4*ii) = rv;
            }
            if (part == 0) hist[s * MTOK + tok] = k;
        }
        __syncthreads();
    }

    // ---- final epilogue: quant = ((q0+q1)+q2)...+q7, exact order ----
    {
        const int tok = tid & 63;
        const int ec  = tid >> 6;          // 0..7
        const int e0  = ec * 8;
        const int n   = blockIdx.x * MTOK + tok;
        const int b   = n >> 12;
        const int hw  = n & 4095;

        float4 acc[2];
        {
            int k = hist[0 * MTOK + tok];
            const float4* qp = (const float4*)(cb + ((size_t)(0 * KCB + k)) * EDIM + e0);
#pragma unroll
            for (int ii = 0; ii < 2; ii++) acc[ii] = __ldg(qp + ii);
        }
#pragma unroll
        for (int s = 1; s < NCODE; s++) {
            int k = hist[s * MTOK + tok];
            const float4* qp = (const float4*)(cb + ((size_t)(s * KCB + k)) * EDIM + e0);
#pragma unroll
            for (int ii = 0; ii < 2; ii++) {
                float4 q = __ldg(qp + ii);
                acc[ii].x = __fadd_rn(acc[ii].x, q.x);
                acc[ii].y = __fadd_rn(acc[ii].y, q.y);
                acc[ii].z = __fadd_rn(acc[ii].z, q.z);
                acc[ii].w = __fadd_rn(acc[ii].w, q.w);
            }
        }
        float* op = out + (size_t)b * (EDIM * 4096) + hw;
#pragma unroll
        for (int ii = 0; ii < 2; ii++) {
            op[(size_t)(e0 + 4*ii + 0) * 4096] = acc[ii].x;
            op[(size_t)(e0 + 4*ii + 1) * 4096] = acc[ii].y;
            op[(size_t)(e0 + 4*ii + 2) * 4096] = acc[ii].z;
            op[(size_t)(e0 + 4*ii + 3) * 4096] = acc[ii].w;
        }
    }
}

extern "C" void kernel_launch(void* const* d_in, const int* in_sizes, int n_in,
                              void* d_out, int out_size)
{
    const float* emb = (const float*)d_in[0];   // [16,64,64,64]
    const float* cb  = (const float*)d_in[1];   // [8,1024,64]
    float* out = (float*)d_out;
    (void)in_sizes; (void)n_in; (void)out_size;

    cudaFuncSetAttribute(rvq_kernel, cudaFuncAttributeMaxDynamicSharedMemorySize,
                         SMEM_BYTES);

    cbt_kernel<<<dim3(32, 2, 8), dim3(32, 8)>>>(cb);
    cb2_kernel<<<(NCODE * KCB) / 256, 256>>>(cb);
    rvq_kernel<<<NTOK / MTOK, TPB, SMEM_BYTES>>>(emb, cb, out);
}

// round 6
// speedup vs baseline: 3.5291x; 1.1964x over previous
#include <cuda_runtime.h>
#include <cuda_fp16.h>
#include <cuda_bf16.h>
#include <cfloat>
#include <cstdint>

// ResidualVectorQuantizer, exact argmin via bf16-MMA prefilter + scalar verify.
// B=16,E=64,H=64,W=64 -> N=65536 tokens; K=1024, NC=8 stages.
//
// Exact reference numerics (validated rel_err==0 in rounds 1-5):
//   r2  = sequential sum of rounded squares of res (e ascending)
//   dot = sequential fused-FMA over e ascending
//   d   = fl(fl(r2 - fl(2*dot)) + cb2), argmin first-index tie-break
//   res -= q elementwise rounded; quant = ((q0+q1)+...)+q7
// MMA computes approximate scores t~ = cb2 - 2*dot~ (bf16 in, f32 acc,
// fp16-stored); every k with t~ <= min + MARGIN is re-verified exactly.
// MARGIN=2e-3 >= 2x rigorous worst-case |t~ - t| (Cauchy-Schwarz bound
// 2*||res||*||cb||*2*2^-9 + fp16 store <= ~1.05e-3 two-sided).
//
// R6 vs R5: prefilter tf32 m16n8k8 -> bf16 m16n8k16 (2x MACs/instr, faster
// HMMA), B tile packed bf16 pairs (half smem, half B-LDS), A frags 32 regs.

#define NTOK   65536
#define EDIM   64
#define KCB    1024
#define NCODE  8
#define MTOK   64          // tokens per CTA
#define TPB    512
#define NWARP  16
#define GTW    256         // codebook k-gtile width (codewords)
#define BPITCH 264         // B tile pitch in 32-bit words: conflict-free
#define RPITCH 68          // res row pitch (floats)
#define SCP    1032        // score row pitch (halves)
#define CAP    48
#define MARGIN 2e-3f

// packed bf16 pairs along e: word(e2,k) = {lo=cb[k][2e2], hi=cb[k][2e2+1]}
__device__ unsigned g_cbt[NCODE * (EDIM/2) * KCB];
__device__ float    g_cb2[NCODE * KCB];         // exact ||cb||^2

__device__ __forceinline__ unsigned packbf(float lo, float hi) {
    unsigned r;
    asm("cvt.rn.bf16x2.f32 %0, %1, %2;" : "=r"(r) : "f"(hi), "f"(lo));
    return r;
}

__device__ __forceinline__ __half2 u2h2(unsigned u) {
    return *reinterpret_cast<__half2*>(&u);
}

__device__ __forceinline__ void mma_bf16(float& c0, float& c1, float& c2, float& c3,
                                         unsigned a0, unsigned a1, unsigned a2, unsigned a3,
                                         unsigned b0, unsigned b1) {
    asm volatile(
        "mma.sync.aligned.m16n8k16.row.col.f32.bf16.bf16.f32 "
        "{%0,%1,%2,%3}, {%4,%5,%6,%7}, {%8,%9}, {%0,%1,%2,%3};\n"
        : "+f"(c0), "+f"(c1), "+f"(c2), "+f"(c3)
        : "r"(a0), "r"(a1), "r"(a2), "r"(a3), "r"(b0), "r"(b1));
}

// ---- precompute: exact cb2 ----
__global__ void cb2_kernel(const float* __restrict__ cb)
{
    const int i = blockIdx.x * blockDim.x + threadIdx.x;   // 0..8191
    const float* row = cb + (size_t)i * EDIM;
    float c2 = 0.0f;
#pragma unroll
    for (int e = 0; e < EDIM; e++)
        c2 = __fadd_rn(c2, __fmul_rn(row[e], row[e]));
    g_cb2[i] = c2;
}

// ---- precompute: transpose + bf16-pack codebook to [s][e2][k] ----
__global__ void cbt_kernel(const float* __restrict__ cb)
{
    __shared__ float tile[32][33];       // [n_local][e_local]
    const int s  = blockIdx.z;
    const int n0 = blockIdx.x * 32;
    const int e0 = blockIdx.y * 32;
    const int tx = threadIdx.x, ty = threadIdx.y;
#pragma unroll
    for (int i = 0; i < 32; i += 8)
        tile[ty + i][tx] = cb[((size_t)s * KCB + (n0 + ty + i)) * EDIM + e0 + tx];
    __syncthreads();
    // write packed pairs: tx = n_local (coalesced), e2 local 0..15
#pragma unroll
    for (int i = 0; i < 2; i++) {
        int e2l = ty + i * 8;
        unsigned wv = packbf(tile[tx][2*e2l], tile[tx][2*e2l + 1]);
        g_cbt[((size_t)s * (EDIM/2) + (e0/2 + e2l)) * KCB + n0 + tx] = wv;
    }
}

struct Cand {
    int   cnt;
    int   pad[3];
    int   tok[CAP];
    int   kk[CAP];
    float dd[CAP];
};

// smem segment sizes (bytes)
#define SC_BYTES   (MTOK * SCP * 2)            // 132096
#define BS_BYTES   ((EDIM/2) * BPITCH * 4)     // 33792
#define RES_BYTES  (MTOK * RPITCH * 4)         // 17408
#define C2S_BYTES  (GTW * 4)                   // 1024
#define CAND_BYTES (NWARP * (int)sizeof(Cand)) // 9472
#define R2S_BYTES  (MTOK * 4)
#define SEL_BYTES  (MTOK * 4)
#define HIST_BYTES (NCODE * MTOK * 4)
#define SMEM_BYTES (SC_BYTES + BS_BYTES + RES_BYTES + C2S_BYTES + CAND_BYTES + \
                    R2S_BYTES + SEL_BYTES + HIST_BYTES)

__global__ __launch_bounds__(TPB, 1)
void rvq_kernel(const float* __restrict__ emb,
                const float* __restrict__ cb,
                float* __restrict__ out)
{
    extern __shared__ char smem[];
    __half*   sc   = (__half*)smem;                        // [64][SCP]
    unsigned* bsw  = (unsigned*)(smem + SC_BYTES);         // [32][BPITCH]
    float*    res  = (float*)(smem + SC_BYTES + BS_BYTES); // [64][RPITCH]
    float*    c2s  = (float*)(smem + SC_BYTES + BS_BYTES + RES_BYTES);
    Cand*     cands= (Cand*)(smem + SC_BYTES + BS_BYTES + RES_BYTES + C2S_BYTES);
    float*    r2s  = (float*)((char*)cands + CAND_BYTES);
    int*      sel  = (int*)((char*)r2s + R2S_BYTES);
    int*      hist = (int*)((char*)sel + SEL_BYTES);       // [s][tok]

    const int tid  = threadIdx.x;
    const int w    = tid >> 5;      // 0..15
    const int lane = tid & 31;
    const int qr   = lane >> 2;     // 0..7
    const int qc   = lane & 3;      // 0..3
    const int nw   = w & 7;         // n-slice (32 wide)
    const int mh   = w >> 3;        // m-half: m-tiles {2mh, 2mh+1}

    // ---- init: load embeddings into res smem ----
    {
        const int tok = tid & 63;
        const int ec  = tid >> 6;       // 0..7
        const int n   = blockIdx.x * MTOK + tok;
        const int b   = n >> 12;
        const int hw  = n & 4095;
        const float* ep = emb + (size_t)b * (EDIM * 4096) + hw;
#pragma unroll
        for (int j = 0; j < 8; j++) {
            int e = ec * 8 + j;
            res[tok * RPITCH + e] = ep[(size_t)e * 4096];
        }
    }
    __syncthreads();

#pragma unroll 1
    for (int s = 0; s < NCODE; s++) {
        // ---- A fragments: this warp's 2 m-tiles, bf16 packed (32 regs) ----
        // m16n8k16: a0={A[qr][2qc,+1]}, a1={A[qr+8][..]}, a2={A[qr][2qc+8,+1]},
        //           a3={A[qr+8][2qc+8,+1]}, k-base = 16*ks
        unsigned a[2][16];
#pragma unroll
        for (int mtl = 0; mtl < 2; mtl++) {
            int r0 = (mh * 2 + mtl) * 16 + qr;
            const float* p0 = res + (size_t)r0 * RPITCH;
            const float* p1 = p0 + 8 * RPITCH;
#pragma unroll
            for (int ks = 0; ks < 4; ks++) {
                int c = 16 * ks + 2 * qc;
                a[mtl][ks*4+0] = packbf(p0[c],     p0[c+1]);
                a[mtl][ks*4+1] = packbf(p1[c],     p1[c+1]);
                a[mtl][ks*4+2] = packbf(p0[c+8],   p0[c+9]);
                a[mtl][ks*4+3] = packbf(p1[c+8],   p1[c+9]);
            }
        }
        // ---- exact r2 per token (sequential, e ascending) ----
        if (tid < MTOK) {
            const float* rr = res + tid * RPITCH;
            float r2 = 0.0f;
#pragma unroll
            for (int e = 0; e < EDIM; e++)
                r2 = __fadd_rn(r2, __fmul_rn(rr[e], rr[e]));
            r2s[tid] = r2;
        }

        // ---- score pass over K in 4 gtiles of 256 ----
#pragma unroll 1
        for (int gt = 0; gt < 4; gt++) {
            __syncthreads();
            // load packed B gtile into [e2][BPITCH]
            const unsigned* gsrc = g_cbt + ((size_t)s * (EDIM/2)) * KCB + gt * GTW;
#pragma unroll
            for (int j = 0; j < 4; j++) {
                int idx = j * TPB + tid;       // 0..2047
                int e2  = idx >> 6;            // 0..31
                int c4  = idx & 63;
                uint4 v = __ldg((const uint4*)(gsrc + (size_t)e2 * KCB) + c4);
                *(uint4*)(bsw + e2 * BPITCH + c4 * 4) = v;
            }
            if (tid < GTW)
                c2s[tid] = __ldg(g_cb2 + s * KCB + gt * GTW + tid);
            __syncthreads();

            // this warp's 32-wide n-slice, two 16-wide passes, 2 m-tiles
            const int nbase = nw * 32;
#pragma unroll 1
            for (int np = 0; np < 2; np++) {
                const int n0 = nbase + np * 16;
                float acc[2][8];
#pragma unroll
                for (int mtl = 0; mtl < 2; mtl++)
#pragma unroll
                    for (int j = 0; j < 8; j++) acc[mtl][j] = 0.0f;

                const unsigned* bp = bsw + n0 + qr;
#pragma unroll
                for (int ks = 0; ks < 4; ks++) {
                    // conflict-free: bank = 8*qc + qr  (264 % 32 == 8)
                    unsigned b00 = bp[(ks*8     + qc) * BPITCH];
                    unsigned b01 = bp[(ks*8 + 4 + qc) * BPITCH];
                    unsigned b10 = bp[(ks*8     + qc) * BPITCH + 8];
                    unsigned b11 = bp[(ks*8 + 4 + qc) * BPITCH + 8];
#pragma unroll
                    for (int mtl = 0; mtl < 2; mtl++) {
                        mma_bf16(acc[mtl][0], acc[mtl][1], acc[mtl][2], acc[mtl][3],
                                 a[mtl][ks*4], a[mtl][ks*4+1], a[mtl][ks*4+2], a[mtl][ks*4+3],
                                 b00, b01);
                        mma_bf16(acc[mtl][4], acc[mtl][5], acc[mtl][6], acc[mtl][7],
                                 a[mtl][ks*4], a[mtl][ks*4+1], a[mtl][ks*4+2], a[mtl][ks*4+3],
                                 b10, b11);
                    }
                }
                // epilogue: t = cb2 - 2*dot -> fp16 scores
                const int cc0 = n0 + 2*qc;
                const int cc1 = cc0 + 8;
                float2 z0 = *(const float2*)(c2s + cc0);
                float2 z1 = *(const float2*)(c2s + cc1);
                const int g0 = gt * GTW + cc0;
                const int g1 = gt * GTW + cc1;
#pragma unroll
                for (int mtl = 0; mtl < 2; mtl++) {
                    int row0 = (mh * 2 + mtl) * 16 + qr, row1 = row0 + 8;
                    __half2 h00 = __halves2half2(__float2half_rn(fmaf(-2.f, acc[mtl][0], z0.x)),
                                                 __float2half_rn(fmaf(-2.f, acc[mtl][1], z0.y)));
                    __half2 h01 = __halves2half2(__float2half_rn(fmaf(-2.f, acc[mtl][2], z0.x)),
                                                 __float2half_rn(fmaf(-2.f, acc[mtl][3], z0.y)));
                    __half2 h10 = __halves2half2(__float2half_rn(fmaf(-2.f, acc[mtl][4], z1.x)),
                                                 __float2half_rn(fmaf(-2.f, acc[mtl][5], z1.y)));
                    __half2 h11 = __halves2half2(__float2half_rn(fmaf(-2.f, acc[mtl][6], z1.x)),
                                                 __float2half_rn(fmaf(-2.f, acc[mtl][7], z1.y)));
                    *(__half2*)(sc + row0 * SCP + g0) = h00;
                    *(__half2*)(sc + row1 * SCP + g0) = h01;
                    *(__half2*)(sc + row0 * SCP + g1) = h10;
                    *(__half2*)(sc + row1 * SCP + g1) = h11;
                }
            }
        }
        __syncthreads();   // scores complete

        // ---- per-warp verify: tokens w*4 .. w*4+3 ----
        Cand* cd = cands + w;
        if (lane == 0) cd->cnt = 0;
        __syncwarp();
        const int tbase = w * 4;
#pragma unroll 1
        for (int t4 = 0; t4 < 4; t4++) {
            const char* srow = (const char*)(sc + (tbase + t4) * SCP);
            uint4 v[4];
            __half2 bmin[4];                 // per-uint4 block min (8 halves)
            __half2 m = __halves2half2(__half(65504.f), __half(65504.f));
#pragma unroll
            for (int jj = 0; jj < 4; jj++) {
                v[jj] = *(const uint4*)(srow + jj*512 + lane*16);
                __half2 m0 = __hmin2(u2h2(v[jj].x), u2h2(v[jj].y));
                __half2 m1 = __hmin2(u2h2(v[jj].z), u2h2(v[jj].w));
                bmin[jj] = __hmin2(m0, m1);
                m = __hmin2(m, bmin[jj]);
            }
            float lmin = __half2float(__hmin(__low2half(m), __high2half(m)));
#pragma unroll
            for (int off = 16; off; off >>= 1)
                lmin = fminf(lmin, __shfl_xor_sync(0xffffffffu, lmin, off));
            const float thr = lmin + MARGIN;
#pragma unroll
            for (int jj = 0; jj < 4; jj++) {
                float bm = __half2float(__hmin(__low2half(bmin[jj]), __high2half(bmin[jj])));
                if (bm <= thr) {           // rare: fine-scan this 8-wide block
                    int kb = jj*256 + lane*8;
                    unsigned uu[4] = {v[jj].x, v[jj].y, v[jj].z, v[jj].w};
#pragma unroll
                    for (int mm = 0; mm < 4; mm++) {
                        __half2 h = u2h2(uu[mm]);
                        if (__half2float(__low2half(h)) <= thr) {
                            int p = atomicAdd(&cd->cnt, 1);
                            if (p < CAP) { cd->tok[p] = t4; cd->kk[p] = kb + 2*mm; }
                        }
                        if (__half2float(__high2half(h)) <= thr) {
                            int p = atomicAdd(&cd->cnt, 1);
                            if (p < CAP) { cd->tok[p] = t4; cd->kk[p] = kb + 2*mm + 1; }
                        }
                    }
                }
            }
        }
        __syncwarp();
        int ncand = min(cd->cnt, CAP);
        // parallel exact evaluation of all candidates (reference numerics)
        for (int base = 0; base < ncand; base += 32) {
            int i = base + lane;
            if (i < ncand) {
                int t4 = cd->tok[i];
                int k  = cd->kk[i];
                int tok = tbase + t4;
                const float4* q4 = (const float4*)(cb + ((size_t)(s * KCB + k)) * EDIM);
                float4 q[16];
#pragma unroll
                for (int ii = 0; ii < 16; ii++) q[ii] = __ldg(q4 + ii);
                const float* rr = res + tok * RPITCH;
                float dot = 0.0f;
#pragma unroll
                for (int ii = 0; ii < 16; ii++) {
                    dot = __fmaf_rn(rr[4*ii+0], q[ii].x, dot);
                    dot = __fmaf_rn(rr[4*ii+1], q[ii].y, dot);
                    dot = __fmaf_rn(rr[4*ii+2], q[ii].z, dot);
                    dot = __fmaf_rn(rr[4*ii+3], q[ii].w, dot);
                }
                float cb2 = __ldg(g_cb2 + s * KCB + k);
                cd->dd[i] = __fadd_rn(__fsub_rn(r2s[tok], __fmul_rn(2.0f, dot)), cb2);
            }
        }
        __syncwarp();
        // per-token select with first-index tie-break
        if (lane < 4) {
            float bd = FLT_MAX; int bk = KCB;
            for (int i = 0; i < ncand; i++) {
                if (cd->tok[i] == lane) {
                    float d = cd->dd[i]; int k = cd->kk[i];
                    if (d < bd || (d == bd && k < bk)) { bd = d; bk = k; }
                }
            }
            sel[tbase + lane] = bk;
        }
        __syncthreads();

        // ---- residual update (exact) ----
        {
            int tok  = tid >> 3;           // 0..63
            int part = tid & 7;            // 0..7, 8 floats each
            int k    = sel[tok];
            const float4* qp = (const float4*)(cb + ((size_t)(s * KCB + k)) * EDIM) + part * 2;
            float* rr = res + tok * RPITCH + part * 8;
#pragma unroll
            for (int ii = 0; ii < 2; ii++) {
                float4 q  = __ldg(qp + ii);
                float4 rv = *(float4*)(rr + 4*ii);
                rv.x = __fsub_rn(rv.x, q.x);
                rv.y = __fsub_rn(rv.y, q.y);
                rv.z = __fsub_rn(rv.z, q.z);
                rv.w = __fsub_rn(rv.w, q.w);
                *(float4*)(rr + 4*ii) = rv;
            }
            if (part == 0) hist[s * MTOK + tok] = k;
        }
        __syncthreads();
    }

    // ---- final epilogue: quant = ((q0+q1)+q2)...+q7, exact order ----
    {
        const int tok = tid & 63;
        const int ec  = tid >> 6;          // 0..7
        const int e0  = ec * 8;
        const int n   = blockIdx.x * MTOK + tok;
        const int b   = n >> 12;
        const int hw  = n & 4095;

        float4 acc[2];
        {
            int k = hist[0 * MTOK + tok];
            const float4* qp = (const float4*)(cb + ((size_t)(0 * KCB + k)) * EDIM + e0);
#pragma unroll
            for (int ii = 0; ii < 2; ii++) acc[ii] = __ldg(qp + ii);
        }
#pragma unroll
        for (int s = 1; s < NCODE; s++) {
            int k = hist[s * MTOK + tok];
            const float4* qp = (const float4*)(cb + ((size_t)(s * KCB + k)) * EDIM + e0);
#pragma unroll
            for (int ii = 0; ii < 2; ii++) {
                float4 q = __ldg(qp + ii);
                acc[ii].x = __fadd_rn(acc[ii].x, q.x);
                acc[ii].y = __fadd_rn(acc[ii].y, q.y);
                acc[ii].z = __fadd_rn(acc[ii].z, q.z);
                acc[ii].w = __fadd_rn(acc[ii].w, q.w);
            }
        }
        float* op = out + (size_t)b * (EDIM * 4096) + hw;
#pragma unroll
        for (int ii = 0; ii < 2; ii++) {
            op[(size_t)(e0 + 4*ii + 0) * 4096] = acc[ii].x;
            op[(size_t)(e0 + 4*ii + 1) * 4096] = acc[ii].y;
            op[(size_t)(e0 + 4*ii + 2) * 4096] = acc[ii].z;
            op[(size_t)(e0 + 4*ii + 3) * 4096] = acc[ii].w;
        }
    }
}

extern "C" void kernel_launch(void* const* d_in, const int* in_sizes, int n_in,
                              void* d_out, int out_size)
{
    const float* emb = (const float*)d_in[0];   // [16,64,64,64]
    const float* cb  = (const float*)d_in[1];   // [8,1024,64]
    float* out = (float*)d_out;
    (void)in_sizes; (void)n_in; (void)out_size;

    cudaFuncSetAttribute(rvq_kernel, cudaFuncAttributeMaxDynamicSharedMemorySize,
                         SMEM_BYTES);

    cbt_kernel<<<dim3(32, 2, 8), dim3(32, 8)>>>(cb);
    cb2_kernel<<<(NCODE * KCB) / 256, 256>>>(cb);
    rvq_kernel<<<NTOK / MTOK, TPB, SMEM_BYTES>>>(emb, cb, out);
}